// round 4
// baseline (speedup 1.0000x reference)
#include <cuda_runtime.h>

// Problem constants
#define NN 100000
#define EE 1600000
#define HID 128
#define NCLS 40
#define NB 391              // ceil(NN/256)

// ---------------- device scratch (static; no cudaMalloc allowed) ----------------
__device__ float g_tmp[(size_t)NN * HID];   // GEMM output (pre-scaled by dinv[src])
__device__ float g_h1[(size_t)NN * HID];    // layer-1 hidden
__device__ float g_dinv[NN];
__device__ int   g_deg[NN];                 // in-degree incl self loop
__device__ int   g_rowptr[NN + 1];
__device__ int   g_cursor[NN];
__device__ int   g_col[EE + NN];
__device__ int   g_bsum[512];
__device__ int   g_fmt;                     // 1 = edge_index is int64, 0 = int32

// ---------------- edge dtype detection ----------------
// int64 node ids < 100000 have zero high words at every odd int32 position.
__global__ void k_detect(const int* __restrict__ ei) {
    if (blockIdx.x == 0 && threadIdx.x == 0) {
        int is64 = 1;
        #pragma unroll
        for (int i = 1; i < 64; i += 2) is64 &= (ei[i] == 0);
        g_fmt = is64;
    }
}

__device__ __forceinline__ int edge_at(const void* __restrict__ ei, size_t idx) {
    if (g_fmt) return (int)((const long long*)ei)[idx];
    return ((const int*)ei)[idx];
}

// ---------------- CSR build ----------------
__global__ void k_init_deg() {
    int i = blockIdx.x * blockDim.x + threadIdx.x;
    if (i < NN) g_deg[i] = 1;   // self loop
}

__global__ void k_count(const void* __restrict__ ei) {
    int e = blockIdx.x * blockDim.x + threadIdx.x;
    if (e < EE) {
        int d = edge_at(ei, (size_t)EE + e);
        if ((unsigned)d < NN) atomicAdd(&g_deg[d], 1);
    }
}

__global__ void k_scan1() {
    __shared__ int s[256];
    int b = blockIdx.x, t = threadIdx.x;
    int i = b * 256 + t;
    int v = (i < NN) ? g_deg[i] : 0;
    s[t] = v;
    __syncthreads();
    #pragma unroll
    for (int off = 1; off < 256; off <<= 1) {
        int add = (t >= off) ? s[t - off] : 0;
        __syncthreads();
        s[t] += add;
        __syncthreads();
    }
    if (i < NN) g_rowptr[i] = s[t] - v;        // exclusive within block
    if (t == 255) g_bsum[b] = s[255];
}

__global__ void k_scan2() {
    __shared__ int s[512];
    int t = threadIdx.x;
    int v = (t < NB) ? g_bsum[t] : 0;
    s[t] = v;
    __syncthreads();
    #pragma unroll
    for (int off = 1; off < 512; off <<= 1) {
        int add = (t >= off) ? s[t - off] : 0;
        __syncthreads();
        s[t] += add;
        __syncthreads();
    }
    if (t < NB) g_bsum[t] = s[t] - v;          // exclusive block offsets
}

__global__ void k_scan3() {
    int b = blockIdx.x, t = threadIdx.x;
    int i = b * 256 + t;
    if (i < NN) g_rowptr[i] += g_bsum[b];
    if (i == 0) g_rowptr[NN] = EE + NN;
}

__global__ void k_selfloop() {
    int i = blockIdx.x * blockDim.x + threadIdx.x;
    if (i < NN) {
        int rp = g_rowptr[i];
        if ((unsigned)rp < (unsigned)(EE + NN)) g_col[rp] = i;  // self loop at slot 0
        g_cursor[i] = 1;
        g_dinv[i] = rsqrtf((float)g_deg[i]);
    }
}

__global__ void k_fill(const void* __restrict__ ei) {
    int e = blockIdx.x * blockDim.x + threadIdx.x;
    if (e < EE) {
        int s = edge_at(ei, e);
        int d = edge_at(ei, (size_t)EE + e);
        if ((unsigned)d < NN) {
            int pos = atomicAdd(&g_cursor[d], 1);
            int w = g_rowptr[d] + pos;
            int c = ((unsigned)s < NN) ? s : d;
            if ((unsigned)w < (unsigned)(EE + NN)) g_col[w] = c;
        }
    }
}

// ---------------- GEMM: g_tmp[m][n] = (A[m][:] . W[:][n]) * dinv[m] ----------------
// BM=64, BN=64, K in 2 chunks of 64. 256 threads, 4x4 microtile. Static smem 33.4KB.
template<int SRC>   // 0: read A param, 1: read g_h1
__global__ void k_gemm(const float* __restrict__ A, const float* __restrict__ W) {
    __shared__ float Ws[64][64];
    __shared__ float Xs[64][68];
    const float* Ain = (SRC == 0) ? A : (const float*)g_h1;
    int t = threadIdx.x;
    int m0 = blockIdx.x * 64;
    int n0 = blockIdx.y * 64;
    int tx = t & 15, ty = t >> 4;
    int rb = ty * 4, cb = tx * 4;
    float acc[4][4];
    #pragma unroll
    for (int r = 0; r < 4; r++)
        #pragma unroll
        for (int c = 0; c < 4; c++) acc[r][c] = 0.f;

    #pragma unroll
    for (int kc = 0; kc < HID; kc += 64) {
        #pragma unroll
        for (int i = 0; i < 4; i++) {
            int idx = t + i * 256;          // float4 index, 0..1023
            int row = idx >> 4;             // k-row 0..63
            int c4 = idx & 15;              // float4 col
            *(float4*)&Ws[row][c4 * 4] =
                *(const float4*)(W + (size_t)(kc + row) * HID + n0 + c4 * 4);
        }
        #pragma unroll
        for (int i = 0; i < 4; i++) {
            int idx = t + i * 256;
            int r = idx >> 4;               // local row 0..63
            int kq = idx & 15;              // float4 along k
            int grow = m0 + r;
            float4 v = make_float4(0.f, 0.f, 0.f, 0.f);
            if (grow < NN) v = *(const float4*)(Ain + (size_t)grow * HID + kc + kq * 4);
            Xs[kq * 4 + 0][r] = v.x;
            Xs[kq * 4 + 1][r] = v.y;
            Xs[kq * 4 + 2][r] = v.z;
            Xs[kq * 4 + 3][r] = v.w;
        }
        __syncthreads();

        #pragma unroll 8
        for (int k = 0; k < 64; k++) {
            float4 xa = *(const float4*)&Xs[k][rb];
            float4 wv = *(const float4*)&Ws[k][cb];
            float xr[4] = {xa.x, xa.y, xa.z, xa.w};
            float wr[4] = {wv.x, wv.y, wv.z, wv.w};
            #pragma unroll
            for (int r = 0; r < 4; r++)
                #pragma unroll
                for (int c = 0; c < 4; c++)
                    acc[r][c] = fmaf(xr[r], wr[c], acc[r][c]);
        }
        __syncthreads();
    }

    #pragma unroll
    for (int r = 0; r < 4; r++) {
        int grow = m0 + rb + r;
        if (grow < NN) {
            float sc = g_dinv[grow];
            float4 o = make_float4(acc[r][0] * sc, acc[r][1] * sc,
                                   acc[r][2] * sc, acc[r][3] * sc);
            *(float4*)(g_tmp + (size_t)grow * HID + n0 + cb) = o;
        }
    }
}

// ---------------- SpMM: out[d] = relu(dinv[d] * sum_{s in N(d)} g_tmp[s] + bias) ----------------
template<int DST>   // 0: write g_h1, 1: write param out
__global__ void k_spmm(const float* __restrict__ bias, float* __restrict__ outp) {
    int gw = (blockIdx.x * blockDim.x + threadIdx.x) >> 5;
    int lane = threadIdx.x & 31;
    if (gw >= NN) return;
    int start = g_rowptr[gw];
    int cnt = g_deg[gw];
    const float* tmp = (const float*)g_tmp;

    float4 acc = make_float4(0.f, 0.f, 0.f, 0.f);
    int j = 0;
    for (; j + 4 <= cnt; j += 4) {
        int s0 = g_col[start + j];
        int s1 = g_col[start + j + 1];
        int s2 = g_col[start + j + 2];
        int s3 = g_col[start + j + 3];
        float4 v0 = *(const float4*)(tmp + (size_t)s0 * HID + lane * 4);
        float4 v1 = *(const float4*)(tmp + (size_t)s1 * HID + lane * 4);
        float4 v2 = *(const float4*)(tmp + (size_t)s2 * HID + lane * 4);
        float4 v3 = *(const float4*)(tmp + (size_t)s3 * HID + lane * 4);
        acc.x += v0.x + v1.x + v2.x + v3.x;
        acc.y += v0.y + v1.y + v2.y + v3.y;
        acc.z += v0.z + v1.z + v2.z + v3.z;
        acc.w += v0.w + v1.w + v2.w + v3.w;
    }
    for (; j < cnt; j++) {
        int s = g_col[start + j];
        float4 v = *(const float4*)(tmp + (size_t)s * HID + lane * 4);
        acc.x += v.x; acc.y += v.y; acc.z += v.z; acc.w += v.w;
    }

    float dv = g_dinv[gw];
    float4 b4 = *(const float4*)(bias + lane * 4);
    float4 o;
    o.x = fmaxf(fmaf(acc.x, dv, b4.x), 0.f);
    o.y = fmaxf(fmaf(acc.y, dv, b4.y), 0.f);
    o.z = fmaxf(fmaf(acc.z, dv, b4.z), 0.f);
    o.w = fmaxf(fmaf(acc.w, dv, b4.w), 0.f);
    float* dst = (DST == 0) ? (float*)g_h1 : outp;
    *(float4*)(dst + (size_t)gw * HID + lane * 4) = o;
}

// ---------------- head GEMM: S[m][c] = H[m][:] . Wh[:][c] + bh[c] ----------------
__global__ void k_gemm3(const float* __restrict__ H, const float* __restrict__ Wh,
                        const float* __restrict__ bh, float* __restrict__ S) {
    __shared__ float Ws[128][40];
    __shared__ float Xs[128][33];
    int t = threadIdx.x;
    int m0 = blockIdx.x * 32;

    for (int i = t; i < 128 * 40; i += 256) ((float*)Ws)[i] = Wh[i];
    #pragma unroll
    for (int i = 0; i < 4; i++) {
        int idx = t + i * 256;          // float4 index, 0..1023
        int r = idx >> 5;               // local row 0..31
        int kq = idx & 31;              // float4 along k
        int grow = m0 + r;
        float4 v = make_float4(0.f, 0.f, 0.f, 0.f);
        if (grow < NN) v = *(const float4*)(H + (size_t)grow * HID + kq * 4);
        Xs[kq * 4 + 0][r] = v.x;
        Xs[kq * 4 + 1][r] = v.y;
        Xs[kq * 4 + 2][r] = v.z;
        Xs[kq * 4 + 3][r] = v.w;
    }
    __syncthreads();

    int tx = t & 7, ty = t >> 3;    // row = ty, cols cb..cb+4
    int cb = tx * 5;
    float acc[5] = {0.f, 0.f, 0.f, 0.f, 0.f};

    #pragma unroll 8
    for (int k = 0; k < 128; k++) {
        float x = Xs[k][ty];
        #pragma unroll
        for (int c = 0; c < 5; c++)
            acc[c] = fmaf(x, Ws[k][cb + c], acc[c]);
    }

    int grow = m0 + ty;
    if (grow < NN) {
        #pragma unroll
        for (int c = 0; c < 5; c++)
            S[(size_t)grow * NCLS + cb + c] = acc[c] + bh[cb + c];
    }
}

// ---------------- launch ----------------
extern "C" void kernel_launch(void* const* d_in, const int* in_sizes, int n_in,
                              void* d_out, int out_size) {
    const float* x   = (const float*)d_in[0];
    const void*  ei  = d_in[1];                 // int32 or int64, detected on device
    const float* W1  = (const float*)d_in[2];
    const float* b1  = (const float*)d_in[3];
    const float* W2  = (const float*)d_in[4];
    const float* b2  = (const float*)d_in[5];
    const float* Wh  = (const float*)d_in[6];
    const float* bh  = (const float*)d_in[7];

    float* out = (float*)d_out;
    float* scores = out;                       // [NN, 40]
    float* h2 = out + (size_t)NN * NCLS;       // [NN, 128]

    const int TB = 256;
    k_detect<<<1, 32>>>((const int*)ei);
    // CSR build
    k_init_deg<<<(NN + TB - 1) / TB, TB>>>();
    k_count<<<(EE + TB - 1) / TB, TB>>>(ei);
    k_scan1<<<NB, TB>>>();
    k_scan2<<<1, 512>>>();
    k_scan3<<<NB, TB>>>();
    k_selfloop<<<(NN + TB - 1) / TB, TB>>>();
    k_fill<<<(EE + TB - 1) / TB, TB>>>(ei);

    dim3 gemm_grid((NN + 63) / 64, 2);
    int spmm_grid = (NN * 32 + TB - 1) / TB;

    // layer 1
    k_gemm<0><<<gemm_grid, TB>>>(x, W1);
    k_spmm<0><<<spmm_grid, TB>>>(b1, nullptr);
    // layer 2 (h2 written straight into output buffer)
    k_gemm<1><<<gemm_grid, TB>>>(x, W2);
    k_spmm<1><<<spmm_grid, TB>>>(b2, h2);
    // head
    k_gemm3<<<(NN + 31) / 32, TB>>>(h2, Wh, bh, scores);
}

// round 5
// speedup vs baseline: 1.2216x; 1.2216x over previous
#include <cuda_runtime.h>

// Problem constants
#define NN 100000
#define EE 1600000
#define HID 128
#define NCLS 40
#define NB 391              // ceil(NN/256)

// ---------------- device scratch (static; no cudaMalloc allowed) ----------------
__device__ float g_tmp[(size_t)NN * HID];   // GEMM output (pre-scaled by dinv[src])
__device__ float g_h1[(size_t)NN * HID];    // layer-1 hidden
__device__ float g_dinv[NN];
__device__ int   g_deg[NN];                 // in-degree incl self loop
__device__ int   g_rowptr[NN + 1];
__device__ int   g_cursor[NN];
__device__ int   g_col[EE + NN];
__device__ int   g_bsum[512];
__device__ int   g_fmt;                     // 1 = edge_index is int64, 0 = int32

// ---------------- edge dtype detection ----------------
__global__ void k_detect(const int* __restrict__ ei) {
    if (blockIdx.x == 0 && threadIdx.x == 0) {
        int is64 = 1;
        #pragma unroll
        for (int i = 1; i < 64; i += 2) is64 &= (ei[i] == 0);
        g_fmt = is64;
    }
}

__device__ __forceinline__ int edge_at(const void* __restrict__ ei, size_t idx) {
    if (g_fmt) return (int)((const long long*)ei)[idx];
    return ((const int*)ei)[idx];
}

// ---------------- CSR build ----------------
__global__ void k_init_deg() {
    int i = blockIdx.x * blockDim.x + threadIdx.x;
    if (i < NN) g_deg[i] = 1;   // self loop
}

__global__ void k_count(const void* __restrict__ ei) {
    int e = blockIdx.x * blockDim.x + threadIdx.x;
    if (e < EE) {
        int d = edge_at(ei, (size_t)EE + e);
        if ((unsigned)d < NN) atomicAdd(&g_deg[d], 1);
    }
}

__global__ void k_scan1() {
    __shared__ int s[256];
    int b = blockIdx.x, t = threadIdx.x;
    int i = b * 256 + t;
    int v = (i < NN) ? g_deg[i] : 0;
    s[t] = v;
    __syncthreads();
    #pragma unroll
    for (int off = 1; off < 256; off <<= 1) {
        int add = (t >= off) ? s[t - off] : 0;
        __syncthreads();
        s[t] += add;
        __syncthreads();
    }
    if (i < NN) g_rowptr[i] = s[t] - v;
    if (t == 255) g_bsum[b] = s[255];
}

__global__ void k_scan2() {
    __shared__ int s[512];
    int t = threadIdx.x;
    int v = (t < NB) ? g_bsum[t] : 0;
    s[t] = v;
    __syncthreads();
    #pragma unroll
    for (int off = 1; off < 512; off <<= 1) {
        int add = (t >= off) ? s[t - off] : 0;
        __syncthreads();
        s[t] += add;
        __syncthreads();
    }
    if (t < NB) g_bsum[t] = s[t] - v;
}

__global__ void k_scan3() {
    int b = blockIdx.x, t = threadIdx.x;
    int i = b * 256 + t;
    if (i < NN) g_rowptr[i] += g_bsum[b];
    if (i == 0) g_rowptr[NN] = EE + NN;
}

__global__ void k_selfloop() {
    int i = blockIdx.x * blockDim.x + threadIdx.x;
    if (i < NN) {
        int rp = g_rowptr[i];
        if ((unsigned)rp < (unsigned)(EE + NN)) g_col[rp] = i;
        g_cursor[i] = 1;
        g_dinv[i] = rsqrtf((float)g_deg[i]);
    }
}

__global__ void k_fill(const void* __restrict__ ei) {
    int e = blockIdx.x * blockDim.x + threadIdx.x;
    if (e < EE) {
        int s = edge_at(ei, e);
        int d = edge_at(ei, (size_t)EE + e);
        if ((unsigned)d < NN) {
            int pos = atomicAdd(&g_cursor[d], 1);
            int w = g_rowptr[d] + pos;
            int c = ((unsigned)s < NN) ? s : d;
            if ((unsigned)w < (unsigned)(EE + NN)) g_col[w] = c;
        }
    }
}

// ---------------- GEMM: g_tmp[m][n] = (A[m][:] . W[:][n]) * dinv[m] ----------------
// BM=128, BN=128 (full), K chunks of 32. 256 threads, 8x8 microtile.
// 4 LDS.128 per 64 FFMA = smem-bandwidth balanced. Smem 33.4KB static.
template<int SRC>   // 0: read A param, 1: read g_h1
__global__ void __launch_bounds__(256, 2)
k_gemm(const float* __restrict__ A, const float* __restrict__ W) {
    __shared__ float Ws[32][128];
    __shared__ float Xs[32][132];
    const float* Ain = (SRC == 0) ? A : (const float*)g_h1;
    int t = threadIdx.x;
    int m0 = blockIdx.x * 128;
    int tx = t & 15, ty = t >> 4;
    int rb = ty * 8, cb = tx * 8;
    float acc[8][8];
    #pragma unroll
    for (int r = 0; r < 8; r++)
        #pragma unroll
        for (int c = 0; c < 8; c++) acc[r][c] = 0.f;

    #pragma unroll
    for (int kc = 0; kc < HID; kc += 32) {
        // stage W chunk [32k][128n]
        #pragma unroll
        for (int i = 0; i < 4; i++) {
            int idx = t + i * 256;          // 0..1023 float4 slots
            int row = idx >> 5;             // k-row 0..31
            int c4 = idx & 31;              // float4 col
            *(float4*)&Ws[row][c4 * 4] =
                *(const float4*)(W + (size_t)(kc + row) * HID + c4 * 4);
        }
        // stage A chunk transposed: Xs[k][m]
        #pragma unroll
        for (int i = 0; i < 4; i++) {
            int idx = t + i * 256;          // 0..1023
            int r = idx >> 3;               // local row 0..127
            int kq = idx & 7;               // float4 along k
            int grow = m0 + r;
            float4 v = make_float4(0.f, 0.f, 0.f, 0.f);
            if (grow < NN) v = *(const float4*)(Ain + (size_t)grow * HID + kc + kq * 4);
            Xs[kq * 4 + 0][r] = v.x;
            Xs[kq * 4 + 1][r] = v.y;
            Xs[kq * 4 + 2][r] = v.z;
            Xs[kq * 4 + 3][r] = v.w;
        }
        __syncthreads();

        #pragma unroll 8
        for (int k = 0; k < 32; k++) {
            float4 x0 = *(const float4*)&Xs[k][rb];
            float4 x1 = *(const float4*)&Xs[k][rb + 4];
            float4 w0 = *(const float4*)&Ws[k][cb];
            float4 w1 = *(const float4*)&Ws[k][cb + 4];
            float xr[8] = {x0.x, x0.y, x0.z, x0.w, x1.x, x1.y, x1.z, x1.w};
            float wr[8] = {w0.x, w0.y, w0.z, w0.w, w1.x, w1.y, w1.z, w1.w};
            #pragma unroll
            for (int r = 0; r < 8; r++)
                #pragma unroll
                for (int c = 0; c < 8; c++)
                    acc[r][c] = fmaf(xr[r], wr[c], acc[r][c]);
        }
        __syncthreads();
    }

    #pragma unroll
    for (int r = 0; r < 8; r++) {
        int grow = m0 + rb + r;
        if (grow < NN) {
            float sc = g_dinv[grow];
            float4 o0 = make_float4(acc[r][0] * sc, acc[r][1] * sc,
                                    acc[r][2] * sc, acc[r][3] * sc);
            float4 o1 = make_float4(acc[r][4] * sc, acc[r][5] * sc,
                                    acc[r][6] * sc, acc[r][7] * sc);
            *(float4*)(g_tmp + (size_t)grow * HID + cb) = o0;
            *(float4*)(g_tmp + (size_t)grow * HID + cb + 4) = o1;
        }
    }
}

// ---------------- SpMM: out[d] = relu(dinv[d] * sum_{s in N(d)} g_tmp[s] + bias) ----------------
template<int DST>   // 0: write g_h1, 1: write param out
__global__ void k_spmm(const float* __restrict__ bias, float* __restrict__ outp) {
    int gw = (blockIdx.x * blockDim.x + threadIdx.x) >> 5;
    int lane = threadIdx.x & 31;
    if (gw >= NN) return;
    int start = g_rowptr[gw];
    int cnt = g_deg[gw];
    const float* tmp = (const float*)g_tmp;

    float4 acc = make_float4(0.f, 0.f, 0.f, 0.f);
    int j = 0;
    for (; j + 4 <= cnt; j += 4) {
        int s0 = g_col[start + j];
        int s1 = g_col[start + j + 1];
        int s2 = g_col[start + j + 2];
        int s3 = g_col[start + j + 3];
        float4 v0 = *(const float4*)(tmp + (size_t)s0 * HID + lane * 4);
        float4 v1 = *(const float4*)(tmp + (size_t)s1 * HID + lane * 4);
        float4 v2 = *(const float4*)(tmp + (size_t)s2 * HID + lane * 4);
        float4 v3 = *(const float4*)(tmp + (size_t)s3 * HID + lane * 4);
        acc.x += v0.x + v1.x + v2.x + v3.x;
        acc.y += v0.y + v1.y + v2.y + v3.y;
        acc.z += v0.z + v1.z + v2.z + v3.z;
        acc.w += v0.w + v1.w + v2.w + v3.w;
    }
    for (; j < cnt; j++) {
        int s = g_col[start + j];
        float4 v = *(const float4*)(tmp + (size_t)s * HID + lane * 4);
        acc.x += v.x; acc.y += v.y; acc.z += v.z; acc.w += v.w;
    }

    float dv = g_dinv[gw];
    float4 b4 = *(const float4*)(bias + lane * 4);
    float4 o;
    o.x = fmaxf(fmaf(acc.x, dv, b4.x), 0.f);
    o.y = fmaxf(fmaf(acc.y, dv, b4.y), 0.f);
    o.z = fmaxf(fmaf(acc.z, dv, b4.z), 0.f);
    o.w = fmaxf(fmaf(acc.w, dv, b4.w), 0.f);
    float* dst = (DST == 0) ? (float*)g_h1 : outp;
    *(float4*)(dst + (size_t)gw * HID + lane * 4) = o;
}

// ---------------- head GEMM: S[m][c] = H[m][:] . Wh[:][c] + bh[c] ----------------
// BM=128, K chunks of 64. 256 threads, 4 rows x 5 cols per thread. Smem 44KB static.
__global__ void __launch_bounds__(256)
k_gemm3(const float* __restrict__ H, const float* __restrict__ Wh,
        const float* __restrict__ bh, float* __restrict__ S) {
    __shared__ float Ws[64][40];
    __shared__ float Xs[64][132];
    int t = threadIdx.x;
    int m0 = blockIdx.x * 128;
    int tx = t & 7, ty = t >> 3;    // tx: 5-col group, ty: 4-row group
    int rb = ty * 4, cb = tx * 5;
    float acc[4][5];
    #pragma unroll
    for (int r = 0; r < 4; r++)
        #pragma unroll
        for (int c = 0; c < 5; c++) acc[r][c] = 0.f;

    #pragma unroll
    for (int kc = 0; kc < HID; kc += 64) {
        // stage Wh chunk [64k][40c]
        for (int i = t; i < 64 * 40; i += 256)
            ((float*)Ws)[i] = Wh[(size_t)(kc + (i / 40)) * NCLS + (i % 40)];
        // stage H chunk transposed: Xs[k][m]
        #pragma unroll
        for (int i = 0; i < 8; i++) {
            int idx = t + i * 256;          // 0..2047 float4 slots
            int r = idx >> 4;               // local row 0..127
            int kq = idx & 15;              // float4 along k
            int grow = m0 + r;
            float4 v = make_float4(0.f, 0.f, 0.f, 0.f);
            if (grow < NN) v = *(const float4*)(H + (size_t)grow * HID + kc + kq * 4);
            Xs[kq * 4 + 0][r] = v.x;
            Xs[kq * 4 + 1][r] = v.y;
            Xs[kq * 4 + 2][r] = v.z;
            Xs[kq * 4 + 3][r] = v.w;
        }
        __syncthreads();

        #pragma unroll 8
        for (int k = 0; k < 64; k++) {
            float4 xa = *(const float4*)&Xs[k][rb];
            float xr[4] = {xa.x, xa.y, xa.z, xa.w};
            float w[5];
            #pragma unroll
            for (int c = 0; c < 5; c++) w[c] = Ws[k][cb + c];
            #pragma unroll
            for (int r = 0; r < 4; r++)
                #pragma unroll
                for (int c = 0; c < 5; c++)
                    acc[r][c] = fmaf(xr[r], w[c], acc[r][c]);
        }
        __syncthreads();
    }

    #pragma unroll
    for (int r = 0; r < 4; r++) {
        int grow = m0 + rb + r;
        if (grow < NN) {
            #pragma unroll
            for (int c = 0; c < 5; c++)
                S[(size_t)grow * NCLS + cb + c] = acc[r][c] + bh[cb + c];
        }
    }
}

// ---------------- launch ----------------
extern "C" void kernel_launch(void* const* d_in, const int* in_sizes, int n_in,
                              void* d_out, int out_size) {
    const float* x   = (const float*)d_in[0];
    const void*  ei  = d_in[1];                 // int32 or int64, detected on device
    const float* W1  = (const float*)d_in[2];
    const float* b1  = (const float*)d_in[3];
    const float* W2  = (const float*)d_in[4];
    const float* b2  = (const float*)d_in[5];
    const float* Wh  = (const float*)d_in[6];
    const float* bh  = (const float*)d_in[7];

    float* out = (float*)d_out;
    float* scores = out;                       // [NN, 40]
    float* h2 = out + (size_t)NN * NCLS;       // [NN, 128]

    const int TB = 256;
    k_detect<<<1, 32>>>((const int*)ei);
    // CSR build
    k_init_deg<<<(NN + TB - 1) / TB, TB>>>();
    k_count<<<(EE + TB - 1) / TB, TB>>>(ei);
    k_scan1<<<NB, TB>>>();
    k_scan2<<<1, 512>>>();
    k_scan3<<<NB, TB>>>();
    k_selfloop<<<(NN + TB - 1) / TB, TB>>>();
    k_fill<<<(EE + TB - 1) / TB, TB>>>(ei);

    int gemm_grid = (NN + 127) / 128;
    int spmm_grid = (NN * 32 + TB - 1) / TB;

    // layer 1
    k_gemm<0><<<gemm_grid, TB>>>(x, W1);
    k_spmm<0><<<spmm_grid, TB>>>(b1, nullptr);
    // layer 2 (h2 written straight into output buffer)
    k_gemm<1><<<gemm_grid, TB>>>(x, W2);
    k_spmm<1><<<spmm_grid, TB>>>(b2, h2);
    // head
    k_gemm3<<<gemm_grid, TB>>>(h2, Wh, bh, scores);
}

// round 6
// speedup vs baseline: 1.4007x; 1.1466x over previous
#include <cuda_runtime.h>
#include <cuda_fp16.h>

// Problem constants
#define NN 100000
#define EE 1600000
#define HID 128
#define NCLS 40
#define NB 391              // ceil(NN/256)

// ---------------- device scratch (static; no cudaMalloc allowed) ----------------
__device__ __half g_tmp[(size_t)NN * HID];  // fp16 messages (pre-scaled by dinv[src])
__device__ float  g_h1[(size_t)NN * HID];   // layer-1 hidden (fp32)
__device__ float  g_dinv[NN];
__device__ int    g_deg[NN];                // in-degree incl self loop
__device__ int    g_rowptr[NN + 1];
__device__ int    g_cursor[NN];
__device__ int    g_col[EE + NN];
__device__ int    g_bsum[512];
__device__ int    g_fmt;                    // 1 = edge_index is int64, 0 = int32

// ---------------- CSR build ----------------
// init degrees; thread 0 also detects edge dtype (int64 ids < 1e5 -> odd words zero)
__global__ void k_init_deg(const int* __restrict__ ei) {
    int i = blockIdx.x * blockDim.x + threadIdx.x;
    if (i < NN) g_deg[i] = 1;   // self loop
    if (i == 0) {
        int is64 = 1;
        #pragma unroll
        for (int j = 1; j < 64; j += 2) is64 &= (ei[j] == 0);
        g_fmt = is64;
    }
}

__device__ __forceinline__ int edge_at(const void* __restrict__ ei, size_t idx) {
    if (g_fmt) return (int)((const long long*)ei)[idx];
    return ((const int*)ei)[idx];
}

__global__ void k_count(const void* __restrict__ ei) {
    int e = blockIdx.x * blockDim.x + threadIdx.x;
    if (e < EE) {
        int d = edge_at(ei, (size_t)EE + e);
        if ((unsigned)d < NN) atomicAdd(&g_deg[d], 1);
    }
}

__global__ void k_scan1() {
    __shared__ int s[256];
    int b = blockIdx.x, t = threadIdx.x;
    int i = b * 256 + t;
    int v = (i < NN) ? g_deg[i] : 0;
    s[t] = v;
    __syncthreads();
    #pragma unroll
    for (int off = 1; off < 256; off <<= 1) {
        int add = (t >= off) ? s[t - off] : 0;
        __syncthreads();
        s[t] += add;
        __syncthreads();
    }
    if (i < NN) g_rowptr[i] = s[t] - v;
    if (t == 255) g_bsum[b] = s[255];
}

__global__ void k_scan2() {
    __shared__ int s[512];
    int t = threadIdx.x;
    int v = (t < NB) ? g_bsum[t] : 0;
    s[t] = v;
    __syncthreads();
    #pragma unroll
    for (int off = 1; off < 512; off <<= 1) {
        int add = (t >= off) ? s[t - off] : 0;
        __syncthreads();
        s[t] += add;
        __syncthreads();
    }
    if (t < NB) g_bsum[t] = s[t] - v;
}

__global__ void k_scan3() {
    int b = blockIdx.x, t = threadIdx.x;
    int i = b * 256 + t;
    if (i < NN) g_rowptr[i] += g_bsum[b];
    if (i == 0) g_rowptr[NN] = EE + NN;
}

__global__ void k_selfloop() {
    int i = blockIdx.x * blockDim.x + threadIdx.x;
    if (i < NN) {
        int rp = g_rowptr[i];
        if ((unsigned)rp < (unsigned)(EE + NN)) g_col[rp] = i;
        g_cursor[i] = 1;
        g_dinv[i] = rsqrtf((float)g_deg[i]);
    }
}

__global__ void k_fill(const void* __restrict__ ei) {
    int e = blockIdx.x * blockDim.x + threadIdx.x;
    if (e < EE) {
        int s = edge_at(ei, e);
        int d = edge_at(ei, (size_t)EE + e);
        if ((unsigned)d < NN) {
            int pos = atomicAdd(&g_cursor[d], 1);
            int w = g_rowptr[d] + pos;
            int c = ((unsigned)s < NN) ? s : d;
            if ((unsigned)w < (unsigned)(EE + NN)) g_col[w] = c;
        }
    }
}

// ---------------- GEMM: g_tmp[m][n] = half((A[m][:] . W[:][n]) * dinv[m]) ----------------
// BM=128, BN=128 (full), K chunks of 32. 256 threads, 8x8 microtile.
template<int SRC>   // 0: read A param, 1: read g_h1
__global__ void __launch_bounds__(256, 2)
k_gemm(const float* __restrict__ A, const float* __restrict__ W) {
    __shared__ float Ws[32][128];
    __shared__ float Xs[32][132];
    const float* Ain = (SRC == 0) ? A : (const float*)g_h1;
    int t = threadIdx.x;
    int m0 = blockIdx.x * 128;
    int tx = t & 15, ty = t >> 4;
    int rb = ty * 8, cb = tx * 8;
    float acc[8][8];
    #pragma unroll
    for (int r = 0; r < 8; r++)
        #pragma unroll
        for (int c = 0; c < 8; c++) acc[r][c] = 0.f;

    #pragma unroll
    for (int kc = 0; kc < HID; kc += 32) {
        #pragma unroll
        for (int i = 0; i < 4; i++) {
            int idx = t + i * 256;          // 0..1023 float4 slots
            int row = idx >> 5;             // k-row 0..31
            int c4 = idx & 31;              // float4 col
            *(float4*)&Ws[row][c4 * 4] =
                *(const float4*)(W + (size_t)(kc + row) * HID + c4 * 4);
        }
        #pragma unroll
        for (int i = 0; i < 4; i++) {
            int idx = t + i * 256;          // 0..1023
            int r = idx >> 3;               // local row 0..127
            int kq = idx & 7;               // float4 along k
            int grow = m0 + r;
            float4 v = make_float4(0.f, 0.f, 0.f, 0.f);
            if (grow < NN) v = *(const float4*)(Ain + (size_t)grow * HID + kc + kq * 4);
            Xs[kq * 4 + 0][r] = v.x;
            Xs[kq * 4 + 1][r] = v.y;
            Xs[kq * 4 + 2][r] = v.z;
            Xs[kq * 4 + 3][r] = v.w;
        }
        __syncthreads();

        #pragma unroll 8
        for (int k = 0; k < 32; k++) {
            float4 x0 = *(const float4*)&Xs[k][rb];
            float4 x1 = *(const float4*)&Xs[k][rb + 4];
            float4 w0 = *(const float4*)&Ws[k][cb];
            float4 w1 = *(const float4*)&Ws[k][cb + 4];
            float xr[8] = {x0.x, x0.y, x0.z, x0.w, x1.x, x1.y, x1.z, x1.w};
            float wr[8] = {w0.x, w0.y, w0.z, w0.w, w1.x, w1.y, w1.z, w1.w};
            #pragma unroll
            for (int r = 0; r < 8; r++)
                #pragma unroll
                for (int c = 0; c < 8; c++)
                    acc[r][c] = fmaf(xr[r], wr[c], acc[r][c]);
        }
        __syncthreads();
    }

    #pragma unroll
    for (int r = 0; r < 8; r++) {
        int grow = m0 + rb + r;
        if (grow < NN) {
            float sc = g_dinv[grow];
            half2 h0 = __floats2half2_rn(acc[r][0] * sc, acc[r][1] * sc);
            half2 h1 = __floats2half2_rn(acc[r][2] * sc, acc[r][3] * sc);
            half2 h2 = __floats2half2_rn(acc[r][4] * sc, acc[r][5] * sc);
            half2 h3 = __floats2half2_rn(acc[r][6] * sc, acc[r][7] * sc);
            uint4 pk;
            pk.x = *(unsigned*)&h0; pk.y = *(unsigned*)&h1;
            pk.z = *(unsigned*)&h2; pk.w = *(unsigned*)&h3;
            *(uint4*)(g_tmp + (size_t)grow * HID + cb) = pk;   // 16B, cb*2 bytes aligned
        }
    }
}

// ---------------- SpMM: out[d] = relu(dinv[d] * sum_{s in N(d)} g_tmp[s] + bias) ----------------
// warp per destination row; fp16 gather (8B/lane per source row), fp32 accumulate.
template<int DST>   // 0: write g_h1, 1: write param out
__global__ void k_spmm(const float* __restrict__ bias, float* __restrict__ outp) {
    int gw = (blockIdx.x * blockDim.x + threadIdx.x) >> 5;
    int lane = threadIdx.x & 31;
    if (gw >= NN) return;
    int start = g_rowptr[gw];
    int cnt = g_deg[gw];
    const __half* tmp = (const __half*)g_tmp;

    float4 acc = make_float4(0.f, 0.f, 0.f, 0.f);
    int j = 0;
    for (; j + 4 <= cnt; j += 4) {
        int s0 = g_col[start + j];
        int s1 = g_col[start + j + 1];
        int s2 = g_col[start + j + 2];
        int s3 = g_col[start + j + 3];
        uint2 u0 = *(const uint2*)(tmp + (size_t)s0 * HID + lane * 4);
        uint2 u1 = *(const uint2*)(tmp + (size_t)s1 * HID + lane * 4);
        uint2 u2 = *(const uint2*)(tmp + (size_t)s2 * HID + lane * 4);
        uint2 u3 = *(const uint2*)(tmp + (size_t)s3 * HID + lane * 4);
        float2 a0 = __half22float2(*(half2*)&u0.x), b0 = __half22float2(*(half2*)&u0.y);
        float2 a1 = __half22float2(*(half2*)&u1.x), b1 = __half22float2(*(half2*)&u1.y);
        float2 a2 = __half22float2(*(half2*)&u2.x), b2 = __half22float2(*(half2*)&u2.y);
        float2 a3 = __half22float2(*(half2*)&u3.x), b3 = __half22float2(*(half2*)&u3.y);
        acc.x += a0.x + a1.x + a2.x + a3.x;
        acc.y += a0.y + a1.y + a2.y + a3.y;
        acc.z += b0.x + b1.x + b2.x + b3.x;
        acc.w += b0.y + b1.y + b2.y + b3.y;
    }
    for (; j < cnt; j++) {
        int s = g_col[start + j];
        uint2 u = *(const uint2*)(tmp + (size_t)s * HID + lane * 4);
        float2 a = __half22float2(*(half2*)&u.x), b = __half22float2(*(half2*)&u.y);
        acc.x += a.x; acc.y += a.y; acc.z += b.x; acc.w += b.y;
    }

    float dv = g_dinv[gw];
    float4 b4 = *(const float4*)(bias + lane * 4);
    float4 o;
    o.x = fmaxf(fmaf(acc.x, dv, b4.x), 0.f);
    o.y = fmaxf(fmaf(acc.y, dv, b4.y), 0.f);
    o.z = fmaxf(fmaf(acc.z, dv, b4.z), 0.f);
    o.w = fmaxf(fmaf(acc.w, dv, b4.w), 0.f);
    float* dst = (DST == 0) ? (float*)g_h1 : outp;
    *(float4*)(dst + (size_t)gw * HID + lane * 4) = o;
}

// ---------------- head GEMM: S[m][c] = H[m][:] . Wh[:][c] + bh[c] ----------------
__global__ void __launch_bounds__(256)
k_gemm3(const float* __restrict__ H, const float* __restrict__ Wh,
        const float* __restrict__ bh, float* __restrict__ S) {
    __shared__ float Ws[64][40];
    __shared__ float Xs[64][132];
    int t = threadIdx.x;
    int m0 = blockIdx.x * 128;
    int tx = t & 7, ty = t >> 3;
    int rb = ty * 4, cb = tx * 5;
    float acc[4][5];
    #pragma unroll
    for (int r = 0; r < 4; r++)
        #pragma unroll
        for (int c = 0; c < 5; c++) acc[r][c] = 0.f;

    #pragma unroll
    for (int kc = 0; kc < HID; kc += 64) {
        for (int i = t; i < 64 * 40; i += 256)
            ((float*)Ws)[i] = Wh[(size_t)(kc + (i / 40)) * NCLS + (i % 40)];
        #pragma unroll
        for (int i = 0; i < 8; i++) {
            int idx = t + i * 256;
            int r = idx >> 4;               // local row 0..127
            int kq = idx & 15;              // float4 along k
            int grow = m0 + r;
            float4 v = make_float4(0.f, 0.f, 0.f, 0.f);
            if (grow < NN) v = *(const float4*)(H + (size_t)grow * HID + kc + kq * 4);
            Xs[kq * 4 + 0][r] = v.x;
            Xs[kq * 4 + 1][r] = v.y;
            Xs[kq * 4 + 2][r] = v.z;
            Xs[kq * 4 + 3][r] = v.w;
        }
        __syncthreads();

        #pragma unroll 8
        for (int k = 0; k < 64; k++) {
            float4 xa = *(const float4*)&Xs[k][rb];
            float xr[4] = {xa.x, xa.y, xa.z, xa.w};
            float w[5];
            #pragma unroll
            for (int c = 0; c < 5; c++) w[c] = Ws[k][cb + c];
            #pragma unroll
            for (int r = 0; r < 4; r++)
                #pragma unroll
                for (int c = 0; c < 5; c++)
                    acc[r][c] = fmaf(xr[r], w[c], acc[r][c]);
        }
        __syncthreads();
    }

    #pragma unroll
    for (int r = 0; r < 4; r++) {
        int grow = m0 + rb + r;
        if (grow < NN) {
            #pragma unroll
            for (int c = 0; c < 5; c++)
                S[(size_t)grow * NCLS + cb + c] = acc[r][c] + bh[cb + c];
        }
    }
}

// ---------------- launch ----------------
extern "C" void kernel_launch(void* const* d_in, const int* in_sizes, int n_in,
                              void* d_out, int out_size) {
    const float* x   = (const float*)d_in[0];
    const void*  ei  = d_in[1];                 // int32 or int64, detected on device
    const float* W1  = (const float*)d_in[2];
    const float* b1  = (const float*)d_in[3];
    const float* W2  = (const float*)d_in[4];
    const float* b2  = (const float*)d_in[5];
    const float* Wh  = (const float*)d_in[6];
    const float* bh  = (const float*)d_in[7];

    float* out = (float*)d_out;
    float* scores = out;                       // [NN, 40]
    float* h2 = out + (size_t)NN * NCLS;       // [NN, 128]

    const int TB = 256;
    // CSR build (detect fused into init)
    k_init_deg<<<(NN + TB - 1) / TB, TB>>>((const int*)ei);
    k_count<<<(EE + TB - 1) / TB, TB>>>(ei);
    k_scan1<<<NB, TB>>>();
    k_scan2<<<1, 512>>>();
    k_scan3<<<NB, TB>>>();
    k_selfloop<<<(NN + TB - 1) / TB, TB>>>();
    k_fill<<<(EE + TB - 1) / TB, TB>>>(ei);

    int gemm_grid = (NN + 127) / 128;
    int spmm_grid = (NN * 32 + TB - 1) / TB;

    // layer 1
    k_gemm<0><<<gemm_grid, TB>>>(x, W1);
    k_spmm<0><<<spmm_grid, TB>>>(b1, nullptr);
    // layer 2 (h2 written straight into output buffer)
    k_gemm<1><<<gemm_grid, TB>>>(x, W2);
    k_spmm<1><<<spmm_grid, TB>>>(b2, h2);
    // head
    k_gemm3<<<gemm_grid, TB>>>(h2, Wh, bh, scores);
}